// round 14
// baseline (speedup 1.0000x reference)
#include <cuda_runtime.h>
#include <math.h>

#define SR_F        48000.0f
#define SOUND_SPEED 343.0f
#define MAX_ORDER   10
#define RIR_LEN     24000
#define TAPS        81
#define HALF        40
#define AXN         42            // axis-image table size (2*(2*10+1))
#define NVALID      1561          // #(ax,ay,az) triples with tot_order <= 10 (exact)
#define MAXB        8
#define TILE        128           // output samples per tile (= block size)
#define NTILES     188            // ceil(24000/128)
#define CAP         NVALID        // per-tile list capacity (provably sufficient)

// ---------------------------------------------------------------------------
// Compile-time table of valid axis-index triples (tot_order <= MAX_ORDER).
// ---------------------------------------------------------------------------
constexpr int axis_order_ct(int a) {
    int p = (a >= 21) ? 1 : 0;
    int n = a - 21 * p - 10;
    int o1 = n - p; if (o1 < 0) o1 = -o1;
    int o2 = n;     if (o2 < 0) o2 = -o2;
    return o1 + o2;
}

struct ValidTable {
    int v[NVALID];
    constexpr ValidTable() : v() {
        int ord[AXN] = {};
        for (int a = 0; a < AXN; ++a) ord[a] = axis_order_ct(a);
        int s = 0;
        for (int az = 0; az < AXN; ++az)
            for (int ay = 0; ay < AXN; ++ay)
                for (int ax = 0; ax < AXN; ++ax)
                    if (ord[ax] + ord[ay] + ord[az] <= MAX_ORDER)
                        v[s++] = ax + AXN * ay + AXN * AXN * az;
    }
};

__device__ const ValidTable VT = ValidTable();

// ---------------------------------------------------------------------------
// Compile-time window table: {0.5*cos, 0.5*sin}(pi*k/41), k = 0..80.
// ---------------------------------------------------------------------------
constexpr double ct_sin(double x) {
    double term = x, sum = x;
    for (int n = 1; n < 20; ++n) {
        term *= -x * x / (double)((2 * n) * (2 * n + 1));
        sum += term;
    }
    return sum;
}
constexpr double ct_cos(double x) {
    double term = 1.0, sum = 1.0;
    for (int n = 1; n < 20; ++n) {
        term *= -x * x / (double)((2 * n - 1) * (2 * n));
        sum += term;
    }
    return sum;
}

struct WinTable {
    float c[TAPS];
    float s[TAPS];
    constexpr WinTable() : c(), s() {
        const double PI = 3.14159265358979323846;
        for (int k = 0; k < TAPS; ++k) {
            double x = PI * (double)k / 41.0;
            if (x > PI) x -= 2.0 * PI;
            c[k] = (float)(0.5 * ct_cos(x));
            s[k] = (float)(0.5 * ct_sin(x));
        }
    }
};

__device__ const WinTable WT = WinTable();

__constant__ float BETA_POW[11] = {
    1.0f, 0.9f, 0.81f, 0.729f, 0.6561f, 0.59049f,
    0.531441f, 0.4782969f, 0.43046721f, 0.387420489f, 0.3486784401f
};

// Per-tile record lists. g_cnt zero at module load; tile_kernel resets its
// own counter after reading (replay-safe, proven in R7).
__device__ int    g_cnt[MAXB * NTILES];
__device__ float4 g_list[(size_t)MAXB * NTILES * CAP * 2];

__device__ __forceinline__ void decode_axis(int a, float& sign, float& off, int& order)
{
    int p = (a >= 21) ? 1 : 0;
    int n = a - 21 * p - 10;
    sign  = (float)(1 - 2 * p);
    off   = (float)(2 * n);
    order = abs(n - p) + abs(n);
}

// ---------------------------------------------------------------------------
// Kernel 1: build records (proven math) and bin into per-(batch,tile) lists.
// A record at base spans taps [base, base+80] -> at most 2 tiles of 128.
// Also writes origin. d_out layout: [B*RIR_LEN rir][B origin]
// ---------------------------------------------------------------------------
__global__ void __launch_bounds__(256)
bin_kernel(const float* __restrict__ in, float* __restrict__ out, int B, int nrec)
{
    int i = blockIdx.x * blockDim.x + threadIdx.x;

    if (i < B) {
        const float* row = in + i * 9;
        float rx = row[0] * 10.0f, ry = row[1] * 10.0f, rz = row[2] * 10.0f;
        float dx = (row[3] - row[6]) * rx;
        float dy = (row[4] - row[7]) * ry;
        float dz = (row[5] - row[8]) * rz;
        out[B * RIR_LEN + i] =
            40.0f + SR_F * sqrtf(dx * dx + dy * dy + dz * dz) / SOUND_SPEED;
    }
    if (i >= nrec) return;

    int b = i / NVALID;
    int s = i - b * NVALID;
    int img = VT.v[s];
    int ax = img % AXN;
    int ay = (img / AXN) % AXN;
    int az = img / (AXN * AXN);

    float sgx, ofx; int ox; decode_axis(ax, sgx, ofx, ox);
    float sgy, ofy; int oy; decode_axis(ay, sgy, ofy, oy);
    float sgz, ofz; int oz; decode_axis(az, sgz, ofz, oz);

    const float* row = in + b * 9;
    float rx = row[0] * 10.0f, ry = row[1] * 10.0f, rz = row[2] * 10.0f;
    float mx = row[3] * rx,    my = row[4] * ry,    mz = row[5] * rz;
    float sx = row[6] * rx,    sy = row[7] * ry,    sz = row[8] * rz;

    float dx = sgx * sx + ofx * rx - mx;
    float dy = sgy * sy + ofy * ry - my;
    float dz = sgz * sz + ofz * rz - mz;

    float dist = sqrtf(dx * dx + dy * dy + dz * dz);
    float tau  = SR_F * dist / SOUND_SPEED;
    float i0   = floorf(tau);
    float frac = tau - i0;

    int base = (int)i0 + HALF;            // first tap's batch-local sample
    if (base >= RIR_LEN) return;          // contributes nothing

    const float INV_PI = 0.318309886183790672f;
    float amp = BETA_POW[ox + oy + oz] / (4.0f * 3.14159265358979323846f * dist);
    float c   = amp * sinpif(frac) * INV_PI;
    float bb  = (40.0f + frac) * (1.0f / 41.0f);
    float cw, sw;
    sincospif(bb, &sw, &cw);

    float4 e0 = make_float4(__int_as_float(base), frac, amp, c);
    float4 e1 = make_float4(cw, sw, 0.0f, 0.0f);

    int tb = b * NTILES;
    int t0 = base >> 7;                               // TILE = 128
    int s0 = atomicAdd(&g_cnt[tb + t0], 1);
    size_t idx0 = ((size_t)(tb + t0) * CAP + s0) * 2;
    g_list[idx0]     = e0;
    g_list[idx0 + 1] = e1;

    int t1 = (base + TAPS - 1) >> 7;
    if (t1 != t0 && t1 < NTILES) {
        int s1 = atomicAdd(&g_cnt[tb + t1], 1);
        size_t idx1 = ((size_t)(tb + t1) * CAP + s1) * 2;
        g_list[idx1]     = e0;
        g_list[idx1 + 1] = e1;
    }
}

// ---------------------------------------------------------------------------
// Kernel 2: one block per (batch,tile); one thread per output sample.
// Stages the tile's records through smem in chunks of 64 and accumulates
// overlapping taps in a register. Plain coalesced store covers zeroing.
// ---------------------------------------------------------------------------
__global__ void __launch_bounds__(TILE)
tile_kernel(float* __restrict__ out, int B)
{
    int t  = blockIdx.x;                 // 0 .. B*NTILES-1
    int b  = t / NTILES;
    int tl = t - b * NTILES;
    int tstart = tl * TILE;              // batch-local start sample
    int tid = threadIdx.x;
    int sample = tstart + tid;           // batch-local sample this thread owns

    __shared__ int    s_n;
    __shared__ float  s_ct[TAPS], s_st[TAPS];
    __shared__ float4 s_rec[64 * 2];

    if (tid == 0) { s_n = g_cnt[t]; g_cnt[t] = 0; }
    if (tid < TAPS) {
        s_ct[tid] = WT.c[tid];
        s_st[tid] = WT.s[tid];
    }
    __syncthreads();

    int n = s_n;
    float acc = 0.0f;

    for (int ch = 0; ch < n; ch += 64) {
        int m = n - ch; if (m > 64) m = 64;
        if (ch) __syncthreads();
        if (tid < 2 * m)
            s_rec[tid] = g_list[((size_t)t * CAP + ch) * 2 + tid];
        __syncthreads();

        for (int r = 0; r < m; ++r) {
            float4 r0 = s_rec[2 * r];                    // smem broadcast
            int tap = sample - __float_as_int(r0.x);
            if ((unsigned)tap >= (unsigned)TAPS) continue;
            float4 r1 = s_rec[2 * r + 1];
            float frac = r0.y, amp = r0.z, c = r0.w;

            float tt = (float)(tap - HALF) - frac;
            float v;
            if (tt == 0.0f) v = amp;                     // tap==40 && frac==0
            else            v = __fdividef((tap & 1) ? c : -c, tt);
            if (tap == 0 && frac > 0.0f) v = 0.0f;       // |t| > HALF edge

            float win = fmaf(s_ct[tap], r1.x, fmaf(s_st[tap], r1.y, 0.5f));
            acc = fmaf(v, win, acc);
        }
    }

    if (sample < RIR_LEN)
        out[b * RIR_LEN + sample] = acc;
}

extern "C" void kernel_launch(void* const* d_in, const int* in_sizes, int n_in,
                              void* d_out, int out_size)
{
    const float* in = (const float*)d_in[0];
    float* out = (float*)d_out;
    int B = in_sizes[0] / 9;
    if (B > MAXB) B = MAXB;

    int nrec = B * NVALID;                        // 12488
    bin_kernel<<<(nrec + 255) / 256, 256>>>(in, out, B, nrec);

    tile_kernel<<<B * NTILES, TILE>>>(out, B);
}

// round 15
// speedup vs baseline: 1.2071x; 1.2071x over previous
#include <cuda_runtime.h>
#include <math.h>

#define SR_F        48000.0f
#define SOUND_SPEED 343.0f
#define MAX_ORDER   10
#define RIR_LEN     24000
#define TAPS        81
#define HALF        40
#define AXN         42            // axis-image table size (2*(2*10+1))
#define NVALID      1561          // #(ax,ay,az) triples with tot_order <= 10 (exact)
#define MAXB        8
#define TILE        512           // output samples per tile
#define NTILES      47            // ceil(24000/512)
#define HALO        80            // taps extend at most 80 past base
#define SMW         (TILE + HALO) // 592 smem cells per slice
#define CAP         NVALID        // per-tile list capacity (provably sufficient)

// ---------------------------------------------------------------------------
// Compile-time table of valid axis-index triples (tot_order <= MAX_ORDER).
// ---------------------------------------------------------------------------
constexpr int axis_order_ct(int a) {
    int p = (a >= 21) ? 1 : 0;
    int n = a - 21 * p - 10;
    int o1 = n - p; if (o1 < 0) o1 = -o1;
    int o2 = n;     if (o2 < 0) o2 = -o2;
    return o1 + o2;
}

struct ValidTable {
    int v[NVALID];
    constexpr ValidTable() : v() {
        int ord[AXN] = {};
        for (int a = 0; a < AXN; ++a) ord[a] = axis_order_ct(a);
        int s = 0;
        for (int az = 0; az < AXN; ++az)
            for (int ay = 0; ay < AXN; ++ay)
                for (int ax = 0; ax < AXN; ++ax)
                    if (ord[ax] + ord[ay] + ord[az] <= MAX_ORDER)
                        v[s++] = ax + AXN * ay + AXN * AXN * az;
    }
};

__device__ const ValidTable VT = ValidTable();

// ---------------------------------------------------------------------------
// Compile-time window table: {0.5*cos, 0.5*sin}(pi*k/41), k = 0..80.
// ---------------------------------------------------------------------------
constexpr double ct_sin(double x) {
    double term = x, sum = x;
    for (int n = 1; n < 20; ++n) {
        term *= -x * x / (double)((2 * n) * (2 * n + 1));
        sum += term;
    }
    return sum;
}
constexpr double ct_cos(double x) {
    double term = 1.0, sum = 1.0;
    for (int n = 1; n < 20; ++n) {
        term *= -x * x / (double)((2 * n - 1) * (2 * n));
        sum += term;
    }
    return sum;
}

struct WinTable {
    float c[TAPS];
    float s[TAPS];
    constexpr WinTable() : c(), s() {
        const double PI = 3.14159265358979323846;
        for (int k = 0; k < TAPS; ++k) {
            double x = PI * (double)k / 41.0;
            if (x > PI) x -= 2.0 * PI;
            c[k] = (float)(0.5 * ct_cos(x));
            s[k] = (float)(0.5 * ct_sin(x));
        }
    }
};

__device__ const WinTable WT = WinTable();

__constant__ float BETA_POW[11] = {
    1.0f, 0.9f, 0.81f, 0.729f, 0.6561f, 0.59049f,
    0.531441f, 0.4782969f, 0.43046721f, 0.387420489f, 0.3486784401f
};

// Per-tile record lists. g_cnt zero at module load; tile_kernel resets its
// own counter after reading (replay-safe pattern, proven R7/R14).
__device__ int    g_cnt[MAXB * NTILES];
__device__ float4 g_list[(size_t)MAXB * NTILES * CAP * 2];

__device__ __forceinline__ void decode_axis(int a, float& sign, float& off, int& order)
{
    int p = (a >= 21) ? 1 : 0;
    int n = a - 21 * p - 10;
    sign  = (float)(1 - 2 * p);
    off   = (float)(2 * n);
    order = abs(n - p) + abs(n);
}

// ---------------------------------------------------------------------------
// Kernel 1: prep = halo-zero + origin + build&bin.
// Halo = first 80 samples of every tile (the only atomic targets).
// Each record is binned ONCE, into the tile containing its base.
// d_out layout: [B*RIR_LEN rir][B origin]
// ---------------------------------------------------------------------------
#define NHALO4 (MAXB * NTILES * (HALO / 4))   // 7520 float4 halo stores (B=8)

__global__ void __launch_bounds__(256)
prep_kernel(const float* __restrict__ in, float* __restrict__ out, int B, int nrec)
{
    int i = blockIdx.x * blockDim.x + threadIdx.x;

    // halo zeroing (20 float4 per tile)
    int nhalo4 = B * NTILES * (HALO / 4);
    if (i < nhalo4) {
        int t   = i / (HALO / 4);
        int o4  = i - t * (HALO / 4);
        int b   = t / NTILES;
        int tl  = t - b * NTILES;
        float4* dst = (float4*)(out + b * RIR_LEN + tl * TILE) + o4;
        *dst = make_float4(0.f, 0.f, 0.f, 0.f);
    }

    if (i < B) {
        const float* row = in + i * 9;
        float rx = row[0] * 10.0f, ry = row[1] * 10.0f, rz = row[2] * 10.0f;
        float dx = (row[3] - row[6]) * rx;
        float dy = (row[4] - row[7]) * ry;
        float dz = (row[5] - row[8]) * rz;
        out[B * RIR_LEN + i] =
            40.0f + SR_F * sqrtf(dx * dx + dy * dy + dz * dz) / SOUND_SPEED;
    }

    if (i >= nrec) return;

    int b = i / NVALID;
    int s = i - b * NVALID;
    int img = VT.v[s];
    int ax = img % AXN;
    int ay = (img / AXN) % AXN;
    int az = img / (AXN * AXN);

    float sgx, ofx; int ox; decode_axis(ax, sgx, ofx, ox);
    float sgy, ofy; int oy; decode_axis(ay, sgy, ofy, oy);
    float sgz, ofz; int oz; decode_axis(az, sgz, ofz, oz);

    const float* row = in + b * 9;
    float rx = row[0] * 10.0f, ry = row[1] * 10.0f, rz = row[2] * 10.0f;
    float mx = row[3] * rx,    my = row[4] * ry,    mz = row[5] * rz;
    float sx = row[6] * rx,    sy = row[7] * ry,    sz = row[8] * rz;

    float dx = sgx * sx + ofx * rx - mx;
    float dy = sgy * sy + ofy * ry - my;
    float dz = sgz * sz + ofz * rz - mz;

    float dist = sqrtf(dx * dx + dy * dy + dz * dz);
    float tau  = SR_F * dist / SOUND_SPEED;
    float i0   = floorf(tau);
    float frac = tau - i0;

    int base = (int)i0 + HALF;            // first tap's batch-local sample (>=40)
    if (base >= RIR_LEN) return;          // contributes nothing

    const float INV_PI = 0.318309886183790672f;
    float amp = BETA_POW[ox + oy + oz] / (4.0f * 3.14159265358979323846f * dist);
    float c   = amp * sinpif(frac) * INV_PI;
    float bb  = (40.0f + frac) * (1.0f / 41.0f);
    float cw, sw;
    sincospif(bb, &sw, &cw);

    int t0 = b * NTILES + (base / TILE);
    int s0 = atomicAdd(&g_cnt[t0], 1);
    size_t idx = ((size_t)t0 * CAP + s0) * 2;
    g_list[idx]     = make_float4(__int_as_float(base), frac, amp, c);
    g_list[idx + 1] = make_float4(cw, sw, 0.0f, 0.0f);
}

// ---------------------------------------------------------------------------
// Kernel 2: one block per (batch,tile). 8 warps, each with a PRIVATE 592-float
// smem slice (plain RMW — lanes hit distinct cells within a record, records
// are sequential within a warp -> race-free, no atomics). Records distributed
// round-robin over warps; taps via the proven lane+32k mapping. Then a
// cross-slice reduction; interior samples [tstart+80, tend) are written with
// plain stores (provably single-writer), halo samples with atomicAdd.
// ---------------------------------------------------------------------------
__global__ void __launch_bounds__(256)
tile_kernel(float* __restrict__ out, int B)
{
    int t  = blockIdx.x;                 // 0 .. B*NTILES-1
    int b  = t / NTILES;
    int tl = t - b * NTILES;
    int tstart = tl * TILE;              // batch-local start sample
    int tid  = threadIdx.x;
    int wid  = tid >> 5;
    int lane = tid & 31;

    __shared__ float s_acc[8][SMW];
    __shared__ int   s_n;

    if (tid == 0) { s_n = g_cnt[t]; g_cnt[t] = 0; }
    {   // zero all 8 slices (4736 floats = 1184 float4)
        float4* p = (float4*)&s_acc[0][0];
        #pragma unroll
        for (int i = 0; i < 5; ++i) {
            int j = tid + 256 * i;
            if (j < (8 * SMW) / 4) p[j] = make_float4(0.f, 0.f, 0.f, 0.f);
        }
    }
    __syncthreads();

    // per-thread window constants (taps lane, lane+32, lane+64)
    float ct[3], st[3];
    #pragma unroll
    for (int k = 0; k < 3; ++k) {
        int tap = lane + 32 * k; if (tap > 80) tap = 80;
        ct[k] = __ldg(&WT.c[tap]);
        st[k] = __ldg(&WT.s[tap]);
    }
    const float A0  = (float)(lane - HALF);
    const float sgn = (lane & 1) ? 1.0f : -1.0f;

    int n = s_n;
    const float4* gl = g_list + (size_t)t * CAP * 2;
    float* slice = s_acc[wid];

    for (int r = wid; r < n; r += 8) {
        float4 r0 = __ldg(gl + 2 * r);
        float4 r1 = __ldg(gl + 2 * r + 1);
        int   base_l = __float_as_int(r0.x) - tstart;   // in [0, TILE)
        float frac   = r0.y;
        float amp    = r0.z;
        float cc     = r0.w * sgn;
        float cw     = r1.x;
        float sw     = r1.y;

        #pragma unroll
        for (int k = 0; k < 3; ++k) {
            int tap = lane + 32 * k;
            if (k == 2 && lane > 16) break;             // tap >= 81
            float tt = (A0 + (float)(32 * k)) - frac;
            float v;
            if (tt == 0.0f) v = amp;                    // tap==40 && frac==0
            else            v = __fdividef(cc, tt);
            if (tap == 0 && frac > 0.0f) v = 0.0f;      // |t| > HALF edge

            float win = fmaf(ct[k], cw, fmaf(st[k], sw, 0.5f));
            slice[base_l + tap] += v * win;             // private slice: no race
        }
    }
    __syncthreads();

    // reduce 8 slices + flush
    for (int x = tid; x < SMW; x += 256) {
        float sum = s_acc[0][x] + s_acc[1][x] + s_acc[2][x] + s_acc[3][x]
                  + s_acc[4][x] + s_acc[5][x] + s_acc[6][x] + s_acc[7][x];
        int g = tstart + x;                             // batch-local sample
        if (g >= RIR_LEN) continue;
        float* dst = out + b * RIR_LEN + g;
        if (x >= HALO && x < TILE) *dst = sum;          // interior: single writer
        else atomicAdd(dst, sum);                       // halo: shared with neighbor
    }
}

extern "C" void kernel_launch(void* const* d_in, const int* in_sizes, int n_in,
                              void* d_out, int out_size)
{
    const float* in = (const float*)d_in[0];
    float* out = (float*)d_out;
    int B = in_sizes[0] / 9;
    if (B > MAXB) B = MAXB;

    int nrec = B * NVALID;                        // 12488 (>= halo4 count 7520)
    prep_kernel<<<(nrec + 255) / 256, 256>>>(in, out, B, nrec);

    tile_kernel<<<B * NTILES, 256>>>(out, B);
}

// round 16
// speedup vs baseline: 3.8929x; 3.2250x over previous
#include <cuda_runtime.h>
#include <math.h>

#define SR_F        48000.0f
#define SOUND_SPEED 343.0f
#define MAX_ORDER   10
#define RIR_LEN     24000
#define TAPS        81
#define HALF        40
#define AXN         42            // axis-image table size (2*(2*10+1))
#define NVALID      1561          // #(ax,ay,az) triples with tot_order <= 10 (exact)
#define MAXB        8
#define RPW         4             // records per warp (best measured config)
#define WPB         8             // warps per block (256 threads)

// ---------------------------------------------------------------------------
// Compile-time table of valid axis-index triples (tot_order <= MAX_ORDER),
// packed as ax + 42*ay + 42*42*az. Batch-independent.
// ---------------------------------------------------------------------------
constexpr int axis_order_ct(int a) {
    int p = (a >= 21) ? 1 : 0;
    int n = a - 21 * p - 10;
    int o1 = n - p; if (o1 < 0) o1 = -o1;
    int o2 = n;     if (o2 < 0) o2 = -o2;
    return o1 + o2;
}

struct ValidTable {
    int v[NVALID];
    constexpr ValidTable() : v() {
        int ord[AXN] = {};
        for (int a = 0; a < AXN; ++a) ord[a] = axis_order_ct(a);
        int s = 0;
        for (int az = 0; az < AXN; ++az)
            for (int ay = 0; ay < AXN; ++ay)
                for (int ax = 0; ax < AXN; ++ax)
                    if (ord[ax] + ord[ay] + ord[az] <= MAX_ORDER)
                        v[s++] = ax + AXN * ay + AXN * AXN * az;
    }
};

__device__ const ValidTable VT = ValidTable();

// ---------------------------------------------------------------------------
// Compile-time window table: {0.5*cos, 0.5*sin}(pi*k/41), k = 0..80.
// ---------------------------------------------------------------------------
constexpr double ct_sin(double x) {
    double term = x, sum = x;
    for (int n = 1; n < 20; ++n) {
        term *= -x * x / (double)((2 * n) * (2 * n + 1));
        sum += term;
    }
    return sum;
}
constexpr double ct_cos(double x) {
    double term = 1.0, sum = 1.0;
    for (int n = 1; n < 20; ++n) {
        term *= -x * x / (double)((2 * n - 1) * (2 * n));
        sum += term;
    }
    return sum;
}

struct WinTable {
    float c[TAPS];
    float s[TAPS];
    constexpr WinTable() : c(), s() {
        const double PI = 3.14159265358979323846;
        for (int k = 0; k < TAPS; ++k) {
            double x = PI * (double)k / 41.0;
            if (x > PI) x -= 2.0 * PI;
            c[k] = (float)(0.5 * ct_cos(x));
            s[k] = (float)(0.5 * ct_sin(x));
        }
    }
};

__device__ const WinTable WT = WinTable();

__constant__ float BETA_POW[11] = {
    1.0f, 0.9f, 0.81f, 0.729f, 0.6561f, 0.59049f,
    0.531441f, 0.4782969f, 0.43046721f, 0.387420489f, 0.3486784401f
};

__device__ __forceinline__ void decode_axis(int a, float& sign, float& off, int& order)
{
    int p = (a >= 21) ? 1 : 0;
    int n = a - 21 * p - 10;
    sign  = (float)(1 - 2 * p);
    off   = (float)(2 * n);
    order = abs(n - p) + abs(n);
}

// ---------------------------------------------------------------------------
// Kernel 1: zero the RIR region of d_out (pure float4 stores) and write
// origin. Fires the PDL completion trigger after its stores.
// d_out layout: [B*RIR_LEN floats rir][B floats origin]
// ---------------------------------------------------------------------------
__global__ void __launch_bounds__(256)
zero_kernel(const float* __restrict__ in, float* __restrict__ out, int B, int n4)
{
    int i = blockIdx.x * blockDim.x + threadIdx.x;
    if (i < n4)
        ((float4*)out)[i] = make_float4(0.f, 0.f, 0.f, 0.f);
    if (i < B) {
        const float* row = in + i * 9;
        float rx = row[0] * 10.0f, ry = row[1] * 10.0f, rz = row[2] * 10.0f;
        float dx = (row[3] - row[6]) * rx;
        float dy = (row[4] - row[7]) * ry;
        float dz = (row[5] - row[8]) * rz;
        out[B * RIR_LEN + i] =
            40.0f + SR_F * sqrtf(dx * dx + dy * dy + dz * dz) / SOUND_SPEED;
    }
    cudaTriggerProgrammaticLaunchCompletion();
}

// ---------------------------------------------------------------------------
// Kernel 2: scatter (R13 configuration, RPW=4) launched with PDL.
// Build phase + window-constant loads overlap the zero kernel; the grid
// dependency sync gates only the atomic loop.
// ---------------------------------------------------------------------------
__global__ void __launch_bounds__(256)
scatter_kernel(const float* __restrict__ in, float* __restrict__ out, int nrec)
{
    const int gtid = blockIdx.x * blockDim.x + threadIdx.x;
    const int w    = gtid >> 5;          // global warp id
    const int wloc = threadIdx.x >> 5;   // warp within block
    const int lane = threadIdx.x & 31;
    const int rec0 = w * RPW;

    __shared__ float4 s_rec[WPB][RPW][2];

    if (rec0 >= nrec) return;

    // ---- Build phase: lanes 0..RPW-1 each build one record ----
    if (lane < RPW && rec0 + lane < nrec) {
        int i = rec0 + lane;
        int b = i / NVALID;
        int s = i - b * NVALID;
        int img = VT.v[s];
        int ax = img % AXN;
        int ay = (img / AXN) % AXN;
        int az = img / (AXN * AXN);

        float sgx, ofx; int ox; decode_axis(ax, sgx, ofx, ox);
        float sgy, ofy; int oy; decode_axis(ay, sgy, ofy, oy);
        float sgz, ofz; int oz; decode_axis(az, sgz, ofz, oz);

        const float* row = in + b * 9;
        float rx = row[0] * 10.0f, ry = row[1] * 10.0f, rz = row[2] * 10.0f;
        float mx = row[3] * rx,    my = row[4] * ry,    mz = row[5] * rz;
        float sx = row[6] * rx,    sy = row[7] * ry,    sz = row[8] * rz;

        float dx = sgx * sx + ofx * rx - mx;
        float dy = sgy * sy + ofy * ry - my;
        float dz = sgz * sz + ofz * rz - mz;

        float dist = sqrtf(dx * dx + dy * dy + dz * dz);
        float tau  = SR_F * dist / SOUND_SPEED;
        float i0   = floorf(tau);
        float frac = tau - i0;

        const float INV_PI = 0.318309886183790672f;
        int  bofs   = b * RIR_LEN;
        int  end_g  = bofs + RIR_LEN;
        int  base   = (int)i0 + HALF;
        int  base_g = (base >= RIR_LEN) ? end_g : bofs + base;
        float amp = BETA_POW[ox + oy + oz] / (4.0f * 3.14159265358979323846f * dist);
        float c   = amp * sinpif(frac) * INV_PI;
        float bb  = (40.0f + frac) * (1.0f / 41.0f);
        float cw, sw;
        sincospif(bb, &sw, &cw);

        s_rec[wloc][lane][0] = make_float4(__int_as_float(base_g), frac, amp, c);
        s_rec[wloc][lane][1] = make_float4(cw, sw, __int_as_float(end_g), 0.0f);
    }
    __syncwarp();

    // ---- Per-thread window constants from the compile-time table ----
    float ct[3], st[3];
    #pragma unroll
    for (int k = 0; k < 3; ++k) {
        int tap = lane + 32 * k; if (tap > 80) tap = 80;
        ct[k] = __ldg(&WT.c[tap]);
        st[k] = __ldg(&WT.s[tap]);
    }
    const float A0 = (float)(lane - HALF);           // tap - 40 for k=0
    const float sgn = (lane & 1) ? 1.0f : -1.0f;     // sinc sign, parity of tap

    int nr = nrec - rec0; if (nr > RPW) nr = RPW;

    // Wait for zero_kernel's stores to be visible before issuing atomics.
    cudaGridDependencySynchronize();

    for (int j = 0; j < nr; ++j) {
        float4 r0 = s_rec[wloc][j][0];
        float4 r1 = s_rec[wloc][j][1];
        int   base_g = __float_as_int(r0.x);
        float frac   = r0.y;
        float amp    = r0.z;
        float cc     = r0.w * sgn;       // signed numerator
        float cw     = r1.x;
        float sw     = r1.y;
        int   end_g  = __float_as_int(r1.z);

        #pragma unroll
        for (int k = 0; k < 3; ++k) {
            int tap = lane + 32 * k;
            if (k == 2 && lane > 16) break;          // tap >= 81
            int idx = base_g + tap;
            if (idx >= end_g) continue;

            float t = (A0 + (float)(32 * k)) - frac;
            float v;
            if (t == 0.0f) v = amp;                  // tap==40 && frac==0
            else           v = __fdividef(cc, t);
            if (tap == 0 && frac > 0.0f) v = 0.0f;   // |t| > HALF support edge

            float win = fmaf(ct[k], cw, fmaf(st[k], sw, 0.5f));
            atomicAdd(out + idx, v * win);
        }
    }
}

extern "C" void kernel_launch(void* const* d_in, const int* in_sizes, int n_in,
                              void* d_out, int out_size)
{
    const float* in = (const float*)d_in[0];
    float* out = (float*)d_out;
    int B = in_sizes[0] / 9;
    if (B > MAXB) B = MAXB;

    int n4 = B * (RIR_LEN / 4);                    // 48000 float4s
    zero_kernel<<<(n4 + 255) / 256, 256>>>(in, out, B, n4);

    int nrec   = B * NVALID;                       // 12488
    int nwarps = (nrec + RPW - 1) / RPW;           // 3122
    int blocks = (nwarps * 32 + 255) / 256;        // 391

    // Launch scatter with Programmatic Dependent Launch so its prologue
    // overlaps zero_kernel; the grid-dependency sync gates only the atomics.
    cudaLaunchConfig_t cfg = {};
    cfg.gridDim  = dim3(blocks, 1, 1);
    cfg.blockDim = dim3(256, 1, 1);
    cfg.dynamicSmemBytes = 0;
    cfg.stream = 0;                                // legacy default stream (captured)
    cudaLaunchAttribute attr[1];
    attr[0].id = cudaLaunchAttributeProgrammaticStreamSerialization;
    attr[0].val.programmaticStreamSerializationAllowed = 1;
    cfg.attrs = attr;
    cfg.numAttrs = 1;
    cudaLaunchKernelEx(&cfg, scatter_kernel, in, out, nrec);
}